// round 1
// baseline (speedup 1.0000x reference)
#include <cuda_runtime.h>
#include <cstdint>

#define NMAX 100000
#define EMAX 1600000
#define DIN  256
#define F    64
#define C2   128

// ---------------- scratch (device globals: allocation-free rule) ----------------
__device__ float  g_ZH[(size_t)NMAX * C2];   // Z pre-activation, then H in-place
__device__ float  g_HP[(size_t)NMAX * C2];   // aggregated e*h[dst] per src
__device__ float4 g_Q[NMAX];                 // per-node score scalars (qs_h,qd_h,qs_l,qd_l), pre-scaled by 1/||a||
__device__ float  g_rsh[NMAX];
__device__ float  g_rsl[NMAX];
__device__ float  g_w[6 * F];                // folded a-vector combos
__device__ float  g_scal[4];                 // inv_norm_high, inv_norm_low, theta_high, theta_low
__device__ int    g_maxZ[2];                 // float-bits max |Z| per branch (non-negative -> int cmp ok)
__device__ int    g_maxO;

__device__ __forceinline__ float leaky(float x) { return fmaxf(x, 0.2f * x); }

// ---------------- K0: norms, thetas, folded weight vectors ----------------
__global__ void prep_kernel(const float* __restrict__ ah, const float* __restrict__ al,
                            const float* __restrict__ ch, const float* __restrict__ cl) {
    __shared__ float sh[256], sl[256];
    int t = threadIdx.x;
    float vh = ah[t], vl = al[t];
    sh[t] = vh * vh; sl[t] = vl * vl;
    __syncthreads();
    for (int o = 128; o; o >>= 1) {
        if (t < o) { sh[t] += sh[t + o]; sl[t] += sl[t + o]; }
        __syncthreads();
    }
    if (t == 0) {
        g_scal[0] = 1.0f / sqrtf(sh[0]);
        g_scal[1] = 1.0f / sqrtf(sl[0]);
        float c = ch[0];
        g_scal[2] = (fminf(fmaxf(c + 3.0f, 0.0f), 6.0f) / 3.0f + 1e-6f) * 0.5f;
        c = cl[0];
        g_scal[3] = (fminf(fmaxf(c + 3.0f, 0.0f), 6.0f) / 3.0f + 1e-6f) * 0.5f;
        g_maxZ[0] = 0; g_maxZ[1] = 0; g_maxO = 0;
    }
    if (t < F) {
        g_w[t]         = ah[t]     + ah[2*F+t] + ah[3*F+t];   // wh1 (src, high)
        g_w[F + t]     = ah[F+t]   + ah[2*F+t] - ah[3*F+t];   // wh2 (dst, high)
        g_w[2*F + t]   = al[t];                                // vl1 (hh src, low)
        g_w[3*F + t]   = al[F+t];                              // vl2 (hh dst, low)
        g_w[4*F + t]   = al[2*F+t] + al[3*F+t];                // vl3 (hl src, low)
        g_w[5*F + t]   = al[2*F+t] - al[3*F+t];                // vl4 (hl dst, low)
    }
}

// ---------------- zero accumulators ----------------
__global__ void zero_kernel(int N) {
    size_t total4 = (size_t)N * 32;
    size_t i = (size_t)blockIdx.x * blockDim.x + threadIdx.x;
    size_t stride = (size_t)gridDim.x * blockDim.x;
    float4 z = make_float4(0.f, 0.f, 0.f, 0.f);
    for (size_t j = i; j < total4; j += stride) ((float4*)g_HP)[j] = z;
    for (size_t j = i; j < (size_t)N; j += stride) { g_rsh[j] = 0.f; g_rsl[j] = 0.f; }
}

// ---------------- K1: SGEMM Z = X @ [Wh|Wl], fused max|Z| per branch ----------------
#define BM 128
#define BN 128
#define BK 32

__global__ void __launch_bounds__(256) gemm_kernel(const float* __restrict__ X,
                                                   const float* __restrict__ Wh,
                                                   const float* __restrict__ Wl, int N) {
    __shared__ float As[BK][BM];
    __shared__ float Bs[BK][BN];
    __shared__ int   smax[2];
    int tid  = threadIdx.x;
    int brow = blockIdx.x * BM;
    int tr = tid >> 4, tc = tid & 15;
    float acc[8][8];
    #pragma unroll
    for (int i = 0; i < 8; i++)
        #pragma unroll
        for (int j = 0; j < 8; j++) acc[i][j] = 0.f;

    for (int k0 = 0; k0 < DIN; k0 += BK) {
        #pragma unroll
        for (int i = 0; i < 4; i++) {
            int idx4 = tid + 256 * i;          // 0..1023 float4 slots of 128x32 tile
            int m  = idx4 >> 3;
            int k4 = (idx4 & 7) * 4;
            int grow = brow + m;
            float4 a = (grow < N) ? *(const float4*)(X + (size_t)grow * DIN + k0 + k4)
                                  : make_float4(0.f, 0.f, 0.f, 0.f);
            As[k4 + 0][m] = a.x; As[k4 + 1][m] = a.y;
            As[k4 + 2][m] = a.z; As[k4 + 3][m] = a.w;
        }
        #pragma unroll
        for (int i = 0; i < 4; i++) {
            int idx4 = tid + 256 * i;          // 32x128 tile
            int k = idx4 >> 5;
            int j = (idx4 & 31) * 4;
            float4 b;
            if (j < F) b = *(const float4*)(Wh + (size_t)(k0 + k) * F + j);
            else       b = *(const float4*)(Wl + (size_t)(k0 + k) * F + (j - F));
            *(float4*)&Bs[k][j] = b;
        }
        __syncthreads();
        #pragma unroll
        for (int k = 0; k < BK; k++) {
            float a[8], b[8];
            #pragma unroll
            for (int i = 0; i < 8; i++) a[i] = As[k][tr * 8 + i];
            #pragma unroll
            for (int j = 0; j < 8; j++) b[j] = Bs[k][tc * 8 + j];
            #pragma unroll
            for (int i = 0; i < 8; i++)
                #pragma unroll
                for (int j = 0; j < 8; j++) acc[i][j] = fmaf(a[i], b[j], acc[i][j]);
        }
        __syncthreads();
    }

    if (tid < 2) smax[tid] = 0;
    __syncthreads();
    float mymax = 0.f;
    #pragma unroll
    for (int i = 0; i < 8; i++) {
        int grow = brow + tr * 8 + i;
        if (grow < N) {
            #pragma unroll
            for (int j = 0; j < 8; j += 4) {
                float4 v = make_float4(acc[i][j], acc[i][j+1], acc[i][j+2], acc[i][j+3]);
                *(float4*)&g_ZH[(size_t)grow * C2 + tc * 8 + j] = v;
                mymax = fmaxf(mymax,
                        fmaxf(fmaxf(fabsf(v.x), fabsf(v.y)), fmaxf(fabsf(v.z), fabsf(v.w))));
            }
        }
    }
    atomicMax(&smax[tc >> 3], __float_as_int(mymax));   // tc<8 -> high cols, tc>=8 -> low
    __syncthreads();
    if (tid < 2) atomicMax(&g_maxZ[tid], smax[tid]);
}

// ---------------- K2: relu_bt + per-node score scalars; warp per node ----------------
__device__ __forceinline__ float dot4(float4 h, const float* w, int c) {
    return h.x * w[c] + h.y * w[c + 1] + h.z * w[c + 2] + h.w * w[c + 3];
}

__global__ void act_kernel(int N) {
    int gw   = (int)(((size_t)blockIdx.x * blockDim.x + threadIdx.x) >> 5);
    int lane = threadIdx.x & 31;
    if (gw >= N) return;
    float th = __int_as_float(g_maxZ[0]);
    float tl = __int_as_float(g_maxZ[1]);
    float t  = (lane < 16) ? th : tl;
    float4 z = *(float4*)&g_ZH[(size_t)gw * C2 + lane * 4];
    float4 h;
    h.x = fminf(leaky(z.x), t); h.y = fminf(leaky(z.y), t);
    h.z = fminf(leaky(z.z), t); h.w = fminf(leaky(z.w), t);
    *(float4*)&g_ZH[(size_t)gw * C2 + lane * 4] = h;

    float p0 = 0.f, p1 = 0.f, p2 = 0.f, p3 = 0.f;
    if (lane < 16) {
        int c = lane * 4;
        p0 = dot4(h, g_w, c);            // hh . wh1
        p1 = dot4(h, g_w + F, c);        // hh . wh2
        p2 = dot4(h, g_w + 2 * F, c);    // hh . vl1
        p3 = dot4(h, g_w + 3 * F, c);    // hh . vl2
    } else {
        int c = lane * 4 - F;
        p2 = dot4(h, g_w + 4 * F, c);    // hl . vl3
        p3 = dot4(h, g_w + 5 * F, c);    // hl . vl4
    }
    #pragma unroll
    for (int o = 16; o; o >>= 1) {
        p0 += __shfl_down_sync(0xffffffffu, p0, o);
        p1 += __shfl_down_sync(0xffffffffu, p1, o);
        p2 += __shfl_down_sync(0xffffffffu, p2, o);
        p3 += __shfl_down_sync(0xffffffffu, p3, o);
    }
    if (lane == 0) {
        float inh = g_scal[0], inl = g_scal[1];
        g_Q[gw] = make_float4(p0 * inh, p1 * inh, p2 * inl, p3 * inl);
    }
}

// ---------------- K3: edge aggregation, warp per edge ----------------
__global__ void __launch_bounds__(256) edge_kernel(const int* __restrict__ src,
                                                   const int* __restrict__ dst, int E) {
    int lane = threadIdx.x & 31;
    int gw   = (int)(((size_t)blockIdx.x * blockDim.x + threadIdx.x) >> 5);
    int nw   = (int)(((size_t)gridDim.x * blockDim.x) >> 5);
    for (int e = gw; e < E; e += nw) {
        int s = __ldg(src + e);
        int d = __ldg(dst + e);
        float4 qs = g_Q[s];
        float4 qd = g_Q[d];
        float sc_h = qs.x + qd.y;
        float sc_l = qs.z + qd.w;
        float eh = __expf(-fmaxf(sc_h, 0.2f * sc_h));
        float el = __expf(-fmaxf(sc_l, 0.2f * sc_l));
        float4 hv = *(const float4*)&g_ZH[(size_t)d * C2 + lane * 4];
        float ec  = (lane < 16) ? eh : el;
        float* dp = &g_HP[(size_t)s * C2 + lane * 4];
        asm volatile("red.global.add.v4.f32 [%0], {%1,%2,%3,%4};"
                     :: "l"(__cvta_generic_to_global(dp)),
                        "f"(hv.x * ec), "f"(hv.y * ec), "f"(hv.z * ec), "f"(hv.w * ec)
                     : "memory");
        if (lane == 0)      atomicAdd(&g_rsh[s], eh);
        else if (lane == 1) atomicAdd(&g_rsl[s], el);
    }
}

// ---------------- K4: divide by rowsum+theta, global max of result ----------------
__global__ void fin1_kernel(float* __restrict__ out, int N) {
    __shared__ int bmax;
    if (threadIdx.x == 0) bmax = 0;
    __syncthreads();
    int gw   = (int)(((size_t)blockIdx.x * blockDim.x + threadIdx.x) >> 5);
    int lane = threadIdx.x & 31;
    float m = 0.f;
    if (gw < N) {
        float theta = (lane < 16) ? g_scal[2] : g_scal[3];
        float rs    = (lane < 16) ? g_rsh[gw] : g_rsl[gw];
        float inv   = 1.0f / (rs + theta);
        float4 hp = *(float4*)&g_HP[(size_t)gw * C2 + lane * 4];
        float4 v  = make_float4(hp.x * inv, hp.y * inv, hp.z * inv, hp.w * inv);
        *(float4*)(out + (size_t)gw * C2 + lane * 4) = v;
        m = fmaxf(fmaxf(fabsf(v.x), fabsf(v.y)), fmaxf(fabsf(v.z), fabsf(v.w)));
    }
    #pragma unroll
    for (int o = 16; o; o >>= 1) m = fmaxf(m, __shfl_down_sync(0xffffffffu, m, o));
    if (lane == 0) atomicMax(&bmax, __float_as_int(m));
    __syncthreads();
    if (threadIdx.x == 0) atomicMax(&g_maxO, bmax);
}

// ---------------- K5: final relu_bt on output ----------------
__global__ void fin2_kernel(float* __restrict__ out, int N) {
    size_t total4 = (size_t)N * 32;
    size_t i = (size_t)blockIdx.x * blockDim.x + threadIdx.x;
    size_t stride = (size_t)gridDim.x * blockDim.x;
    float t = __int_as_float(g_maxO);
    for (size_t j = i; j < total4; j += stride) {
        float4 v = ((float4*)out)[j];
        v.x = fminf(leaky(v.x), t); v.y = fminf(leaky(v.y), t);
        v.z = fminf(leaky(v.z), t); v.w = fminf(leaky(v.w), t);
        ((float4*)out)[j] = v;
    }
}

extern "C" void kernel_launch(void* const* d_in, const int* in_sizes, int n_in,
                              void* d_out, int out_size) {
    const float* X    = (const float*)d_in[0];
    const int*   edge = (const int*)d_in[1];
    const float* Wh   = (const float*)d_in[2];
    const float* Wl   = (const float*)d_in[3];
    const float* ah   = (const float*)d_in[4];
    const float* al   = (const float*)d_in[5];
    const float* ch   = (const float*)d_in[6];
    const float* cl   = (const float*)d_in[7];
    float* out = (float*)d_out;

    int N = in_sizes[0] / DIN;
    int E = in_sizes[1] / 2;

    prep_kernel<<<1, 256>>>(ah, al, ch, cl);
    zero_kernel<<<1184, 256>>>(N);
    gemm_kernel<<<(N + BM - 1) / BM, 256>>>(X, Wh, Wl, N);
    act_kernel<<<(N * 32 + 255) / 256, 256>>>(N);
    edge_kernel<<<2048, 256>>>(edge, edge + E, E);
    fin1_kernel<<<(N * 32 + 255) / 256, 256>>>(out, N);
    fin2_kernel<<<2048, 256>>>(out, N);
}

// round 3
// speedup vs baseline: 1.3095x; 1.3095x over previous
#include <cuda_runtime.h>
#include <cuda_bf16.h>
#include <cstdint>

#define NMAX 100000
#define DIN  256
#define F    64
#define C2   128

// ---------------- scratch (device globals: allocation-free rule) ----------------
__device__ float  g_ZH[(size_t)NMAX * C2];   // Z pre-activation, then H in-place
__device__ float  g_HP[(size_t)NMAX * C2];   // aggregated e*h[dst] per src
__device__ float4 g_Q[NMAX];                 // per-node score scalars, pre-scaled by 1/||a||
__device__ float  g_rsh[NMAX];
__device__ float  g_rsl[NMAX];
__device__ float  g_w[6 * F];                // folded a-vector combos
__device__ float  g_scal[4];                 // inv_norm_high, inv_norm_low, theta_high, theta_low
__device__ int    g_maxZ[2];
__device__ int    g_maxO;
// Pre-split, pre-transposed B = [Wh|Wl]: [128 n][256 k] bf16 hi/lo images (L2-hot).
__device__ __align__(16) __nv_bfloat16 g_Bt_h[128 * 256];
__device__ __align__(16) __nv_bfloat16 g_Bt_l[128 * 256];

__device__ __forceinline__ float leaky(float x) { return fmaxf(x, 0.2f * x); }

__device__ __forceinline__ uint32_t smem_u32(const void* p) {
    uint32_t a;
    asm("{ .reg .u64 t; cvta.to.shared.u64 t, %1; cvt.u32.u64 %0, t; }" : "=r"(a) : "l"(p));
    return a;
}

__device__ __forceinline__ void split_bf16(float x, __nv_bfloat16& hi, __nv_bfloat16& lo) {
    hi = __float2bfloat16(x);
    lo = __float2bfloat16(x - __bfloat162float(hi));
}

#define LDMX4(r0, r1, r2, r3, addr) \
    asm volatile("ldmatrix.sync.aligned.m8n8.x4.shared.b16 {%0,%1,%2,%3}, [%4];" \
                 : "=r"(r0), "=r"(r1), "=r"(r2), "=r"(r3) : "r"(addr))

#define MMA16816(d, a, b0, b1) \
    asm volatile("mma.sync.aligned.m16n8k16.row.col.f32.bf16.bf16.f32 " \
                 "{%0,%1,%2,%3}, {%4,%5,%6,%7}, {%8,%9}, {%0,%1,%2,%3};" \
                 : "+f"((d)[0]), "+f"((d)[1]), "+f"((d)[2]), "+f"((d)[3]) \
                 : "r"((a)[0]), "r"((a)[1]), "r"((a)[2]), "r"((a)[3]), "r"(b0), "r"(b1))

// ---------------- K0: norms, thetas, folded weight vectors ----------------
__global__ void prep_kernel(const float* __restrict__ ah, const float* __restrict__ al,
                            const float* __restrict__ ch, const float* __restrict__ cl) {
    __shared__ float sh[256], sl[256];
    int t = threadIdx.x;
    float vh = ah[t], vl = al[t];
    sh[t] = vh * vh; sl[t] = vl * vl;
    __syncthreads();
    for (int o = 128; o; o >>= 1) {
        if (t < o) { sh[t] += sh[t + o]; sl[t] += sl[t + o]; }
        __syncthreads();
    }
    if (t == 0) {
        g_scal[0] = 1.0f / sqrtf(sh[0]);
        g_scal[1] = 1.0f / sqrtf(sl[0]);
        float c = ch[0];
        g_scal[2] = (fminf(fmaxf(c + 3.0f, 0.0f), 6.0f) / 3.0f + 1e-6f) * 0.5f;
        c = cl[0];
        g_scal[3] = (fminf(fmaxf(c + 3.0f, 0.0f), 6.0f) / 3.0f + 1e-6f) * 0.5f;
        g_maxZ[0] = 0; g_maxZ[1] = 0; g_maxO = 0;
    }
    if (t < F) {
        g_w[t]         = ah[t]     + ah[2*F+t] + ah[3*F+t];
        g_w[F + t]     = ah[F+t]   + ah[2*F+t] - ah[3*F+t];
        g_w[2*F + t]   = al[t];
        g_w[3*F + t]   = al[F+t];
        g_w[4*F + t]   = al[2*F+t] + al[3*F+t];
        g_w[5*F + t]   = al[2*F+t] - al[3*F+t];
    }
}

// ---------------- K0b: build split/transposed B images ----------------
__global__ void prep_b_kernel(const float* __restrict__ Wh, const float* __restrict__ Wl) {
    int e = blockIdx.x * blockDim.x + threadIdx.x;   // 0..32767
    int n = e >> 8;
    int k = e & 255;
    float v = (n < 64) ? Wh[(size_t)k * F + n] : Wl[(size_t)k * F + (n - 64)];
    __nv_bfloat16 hi, lo;
    split_bf16(v, hi, lo);
    g_Bt_h[e] = hi;
    g_Bt_l[e] = lo;
}

// ---------------- zero accumulators ----------------
__global__ void zero_kernel(int N) {
    size_t total4 = (size_t)N * 32;
    size_t i = (size_t)blockIdx.x * blockDim.x + threadIdx.x;
    size_t stride = (size_t)gridDim.x * blockDim.x;
    float4 z = make_float4(0.f, 0.f, 0.f, 0.f);
    for (size_t j = i; j < total4; j += stride) ((float4*)g_HP)[j] = z;
    for (size_t j = i; j < (size_t)N; j += stride) { g_rsh[j] = 0.f; g_rsl[j] = 0.f; }
}

// ---------------- K1: HMMA split-bf16 GEMM Z = X @ [Wh|Wl], fused max|Z| ----------------
#define ASTRIDE 40   // bf16 elements per smem row (32 + 8 pad)

__global__ void __launch_bounds__(256) gemm_tc_kernel(const float* __restrict__ X, int N) {
    __shared__ __nv_bfloat16 As_h[128 * ASTRIDE];
    __shared__ __nv_bfloat16 As_l[128 * ASTRIDE];
    __shared__ __nv_bfloat16 Bs_h[128 * ASTRIDE];
    __shared__ __nv_bfloat16 Bs_l[128 * ASTRIDE];
    __shared__ int smax[2];

    int tid  = threadIdx.x;
    int wid  = tid >> 5;
    int lane = tid & 31;
    int brow = blockIdx.x * 128;
    int warp_m = wid & 3;      // 32-row slab
    int warp_n = wid >> 2;     // 64-col slab (0 = high, 1 = low)

    if (tid < 2) smax[tid] = 0;

    float acc[2][8][4];
    #pragma unroll
    for (int mi = 0; mi < 2; mi++)
        #pragma unroll
        for (int ni = 0; ni < 8; ni++)
            #pragma unroll
            for (int q = 0; q < 4; q++) acc[mi][ni][q] = 0.f;

    uint32_t sbAH = smem_u32(As_h), sbAL = smem_u32(As_l);
    uint32_t sbBH = smem_u32(Bs_h), sbBL = smem_u32(Bs_l);

    // ldmatrix address components (element offsets within a row-major padded tile)
    int a_r = lane & 15, a_c = (lane >> 4) << 3;                 // A: 16x16 x4 pattern
    int b_r = lane & 7;
    int b_n = ((lane >> 4) & 1) << 3;                            // +8 n for mats 2,3
    int b_k = ((lane >> 3) & 1) << 3;                            // +8 k for mats 1,3

    for (int chunk = 0; chunk < 8; chunk++) {
        int k0 = chunk * 32;
        // --- A: load X fp32 128x32, split hi/lo -> smem ---
        #pragma unroll
        for (int i = 0; i < 4; i++) {
            int idx = tid + 256 * i;            // 1024 float4 slots
            int row = idx >> 3;
            int c4  = (idx & 7) << 2;
            int grow = brow + row;
            float4 v = (grow < N) ? *(const float4*)(X + (size_t)grow * DIN + k0 + c4)
                                  : make_float4(0.f, 0.f, 0.f, 0.f);
            __nv_bfloat16 h0, h1, h2, h3, l0, l1, l2, l3;
            split_bf16(v.x, h0, l0); split_bf16(v.y, h1, l1);
            split_bf16(v.z, h2, l2); split_bf16(v.w, h3, l3);
            int o = row * ASTRIDE + c4;
            __nv_bfloat162 p;
            p.x = h0; p.y = h1; *(__nv_bfloat162*)&As_h[o]     = p;
            p.x = h2; p.y = h3; *(__nv_bfloat162*)&As_h[o + 2] = p;
            p.x = l0; p.y = l1; *(__nv_bfloat162*)&As_l[o]     = p;
            p.x = l2; p.y = l3; *(__nv_bfloat162*)&As_l[o + 2] = p;
        }
        // --- B: copy pre-split images [128n][32k] -> smem ---
        #pragma unroll
        for (int i = 0; i < 2; i++) {
            int idx = tid + 256 * i;            // 512 uint4 slots per matrix
            int n  = idx >> 2;
            int kk = (idx & 3) << 3;
            uint4 vh = *(const uint4*)(g_Bt_h + (size_t)n * 256 + k0 + kk);
            uint4 vl = *(const uint4*)(g_Bt_l + (size_t)n * 256 + k0 + kk);
            *(uint4*)&Bs_h[n * ASTRIDE + kk] = vh;
            *(uint4*)&Bs_l[n * ASTRIDE + kk] = vl;
        }
        __syncthreads();

        #pragma unroll
        for (int ks = 0; ks < 2; ks++) {
            int k16 = ks * 16;
            uint32_t ah[2][4], al[2][4];
            #pragma unroll
            for (int mi = 0; mi < 2; mi++) {
                uint32_t aoff = ((warp_m * 32 + mi * 16 + a_r) * ASTRIDE + k16 + a_c) * 2;
                LDMX4(ah[mi][0], ah[mi][1], ah[mi][2], ah[mi][3], sbAH + aoff);
                LDMX4(al[mi][0], al[mi][1], al[mi][2], al[mi][3], sbAL + aoff);
            }
            #pragma unroll
            for (int np = 0; np < 4; np++) {
                uint32_t boff = ((warp_n * 64 + np * 16 + b_n + b_r) * ASTRIDE + k16 + b_k) * 2;
                uint32_t bh[4], bl[4];
                LDMX4(bh[0], bh[1], bh[2], bh[3], sbBH + boff);
                LDMX4(bl[0], bl[1], bl[2], bl[3], sbBL + boff);
                #pragma unroll
                for (int mi = 0; mi < 2; mi++) {
                    #pragma unroll
                    for (int h = 0; h < 2; h++) {
                        float* d = acc[mi][np * 2 + h];
                        MMA16816(d, ah[mi], bh[2 * h], bh[2 * h + 1]);
                        MMA16816(d, ah[mi], bl[2 * h], bl[2 * h + 1]);
                        MMA16816(d, al[mi], bh[2 * h], bh[2 * h + 1]);
                    }
                }
            }
        }
        __syncthreads();
    }

    // --- Epilogue: store fragments + per-branch |max| ---
    float mymax = 0.f;
    int row0 = brow + warp_m * 32 + (lane >> 2);
    int col0 = warp_n * 64 + ((lane & 3) << 1);
    #pragma unroll
    for (int mi = 0; mi < 2; mi++) {
        int r0 = row0 + mi * 16;
        #pragma unroll
        for (int ni = 0; ni < 8; ni++) {
            int c = col0 + ni * 8;
            float* d = acc[mi][ni];
            if (r0 < N) {
                *(float2*)&g_ZH[(size_t)r0 * C2 + c] = make_float2(d[0], d[1]);
                mymax = fmaxf(mymax, fmaxf(fabsf(d[0]), fabsf(d[1])));
            }
            if (r0 + 8 < N) {
                *(float2*)&g_ZH[(size_t)(r0 + 8) * C2 + c] = make_float2(d[2], d[3]);
                mymax = fmaxf(mymax, fmaxf(fabsf(d[2]), fabsf(d[3])));
            }
        }
    }
    atomicMax(&smax[warp_n], __float_as_int(mymax));
    __syncthreads();
    if (tid < 2) atomicMax(&g_maxZ[tid], smax[tid]);
}

// ---------------- K2: relu_bt + per-node score scalars; warp per node ----------------
__device__ __forceinline__ float dot4v(float4 h, float4 w) {
    return fmaf(h.x, w.x, fmaf(h.y, w.y, fmaf(h.z, w.z, h.w * w.w)));
}

__global__ void act_kernel(int N) {
    int gw   = (int)(((size_t)blockIdx.x * blockDim.x + threadIdx.x) >> 5);
    int lane = threadIdx.x & 31;
    if (gw >= N) return;
    float th = __int_as_float(g_maxZ[0]);
    float tl = __int_as_float(g_maxZ[1]);
    float t  = (lane < 16) ? th : tl;
    float4 z = *(float4*)&g_ZH[(size_t)gw * C2 + lane * 4];
    float4 h;
    h.x = fminf(leaky(z.x), t); h.y = fminf(leaky(z.y), t);
    h.z = fminf(leaky(z.z), t); h.w = fminf(leaky(z.w), t);
    *(float4*)&g_ZH[(size_t)gw * C2 + lane * 4] = h;

    const float4* W4 = (const float4*)g_w;
    float p0 = 0.f, p1 = 0.f, p2 = 0.f, p3 = 0.f;
    if (lane < 16) {
        p0 = dot4v(h, __ldg(W4 + lane));
        p1 = dot4v(h, __ldg(W4 + 16 + lane));
        p2 = dot4v(h, __ldg(W4 + 32 + lane));
        p3 = dot4v(h, __ldg(W4 + 48 + lane));
    } else {
        p2 = dot4v(h, __ldg(W4 + 48 + lane));        // 64 + (lane-16)
        p3 = dot4v(h, __ldg(W4 + 64 + lane));        // 80 + (lane-16)
    }
    #pragma unroll
    for (int o = 16; o; o >>= 1) {
        p0 += __shfl_down_sync(0xffffffffu, p0, o);
        p1 += __shfl_down_sync(0xffffffffu, p1, o);
        p2 += __shfl_down_sync(0xffffffffu, p2, o);
        p3 += __shfl_down_sync(0xffffffffu, p3, o);
    }
    if (lane == 0) {
        float inh = g_scal[0], inl = g_scal[1];
        g_Q[gw] = make_float4(p0 * inh, p1 * inh, p2 * inl, p3 * inl);
    }
}

// ---------------- K3: edge aggregation, warp per edge ----------------
__global__ void __launch_bounds__(256) edge_kernel(const int* __restrict__ src,
                                                   const int* __restrict__ dst, int E) {
    int lane = threadIdx.x & 31;
    int gw   = (int)(((size_t)blockIdx.x * blockDim.x + threadIdx.x) >> 5);
    int nw   = (int)(((size_t)gridDim.x * blockDim.x) >> 5);
    for (int e = gw; e < E; e += nw) {
        int s = __ldg(src + e);
        int d = __ldg(dst + e);
        float4 qs = g_Q[s];
        float4 qd = g_Q[d];
        float sc_h = qs.x + qd.y;
        float sc_l = qs.z + qd.w;
        float eh = __expf(-fmaxf(sc_h, 0.2f * sc_h));
        float el = __expf(-fmaxf(sc_l, 0.2f * sc_l));
        float4 hv = *(const float4*)&g_ZH[(size_t)d * C2 + lane * 4];
        float ec  = (lane < 16) ? eh : el;
        float* dp = &g_HP[(size_t)s * C2 + lane * 4];
        asm volatile("red.global.add.v4.f32 [%0], {%1,%2,%3,%4};"
                     :: "l"(__cvta_generic_to_global(dp)),
                        "f"(hv.x * ec), "f"(hv.y * ec), "f"(hv.z * ec), "f"(hv.w * ec)
                     : "memory");
        if (lane == 0)      atomicAdd(&g_rsh[s], eh);
        else if (lane == 1) atomicAdd(&g_rsl[s], el);
    }
}

// ---------------- K4: divide by rowsum+theta, global max of result ----------------
__global__ void fin1_kernel(float* __restrict__ out, int N) {
    __shared__ int bmax;
    if (threadIdx.x == 0) bmax = 0;
    __syncthreads();
    int gw   = (int)(((size_t)blockIdx.x * blockDim.x + threadIdx.x) >> 5);
    int lane = threadIdx.x & 31;
    float m = 0.f;
    if (gw < N) {
        float theta = (lane < 16) ? g_scal[2] : g_scal[3];
        float rs    = (lane < 16) ? g_rsh[gw] : g_rsl[gw];
        float inv   = 1.0f / (rs + theta);
        float4 hp = *(float4*)&g_HP[(size_t)gw * C2 + lane * 4];
        float4 v  = make_float4(hp.x * inv, hp.y * inv, hp.z * inv, hp.w * inv);
        *(float4*)(out + (size_t)gw * C2 + lane * 4) = v;
        m = fmaxf(fmaxf(fabsf(v.x), fabsf(v.y)), fmaxf(fabsf(v.z), fabsf(v.w)));
    }
    #pragma unroll
    for (int o = 16; o; o >>= 1) m = fmaxf(m, __shfl_down_sync(0xffffffffu, m, o));
    if (lane == 0) atomicMax(&bmax, __float_as_int(m));
    __syncthreads();
    if (threadIdx.x == 0) atomicMax(&g_maxO, bmax);
}

// ---------------- K5: final relu_bt on output ----------------
__global__ void fin2_kernel(float* __restrict__ out, int N) {
    size_t total4 = (size_t)N * 32;
    size_t i = (size_t)blockIdx.x * blockDim.x + threadIdx.x;
    size_t stride = (size_t)gridDim.x * blockDim.x;
    float t = __int_as_float(g_maxO);
    for (size_t j = i; j < total4; j += stride) {
        float4 v = ((float4*)out)[j];
        v.x = fminf(leaky(v.x), t); v.y = fminf(leaky(v.y), t);
        v.z = fminf(leaky(v.z), t); v.w = fminf(leaky(v.w), t);
        ((float4*)out)[j] = v;
    }
}

extern "C" void kernel_launch(void* const* d_in, const int* in_sizes, int n_in,
                              void* d_out, int out_size) {
    const float* X    = (const float*)d_in[0];
    const int*   edge = (const int*)d_in[1];
    const float* Wh   = (const float*)d_in[2];
    const float* Wl   = (const float*)d_in[3];
    const float* ah   = (const float*)d_in[4];
    const float* al   = (const float*)d_in[5];
    const float* ch   = (const float*)d_in[6];
    const float* cl   = (const float*)d_in[7];
    float* out = (float*)d_out;

    int N = in_sizes[0] / DIN;
    int E = in_sizes[1] / 2;

    prep_kernel<<<1, 256>>>(ah, al, ch, cl);
    prep_b_kernel<<<128, 256>>>(Wh, Wl);
    zero_kernel<<<1184, 256>>>(N);
    gemm_tc_kernel<<<(N + 127) / 128, 256>>>(X, N);
    act_kernel<<<(N * 32 + 255) / 256, 256>>>(N);
    edge_kernel<<<2048, 256>>>(edge, edge + E, E);
    fin1_kernel<<<(N * 32 + 255) / 256, 256>>>(out, N);
    fin2_kernel<<<2048, 256>>>(out, N);
}